// round 1
// baseline (speedup 1.0000x reference)
#include <cuda_runtime.h>
#include <math_constants.h>

#define HH 1024
#define WW 1024
#define CC 128
#define NITER 8

// 3 rotating cluster buffers, each 2*CC floats (row,col interleaved)
__device__ float g_buf[3][2 * CC];

// init: buf0 = input clusters, buf1 = 0 (output of iter 0)
__global__ void km_init_kernel(const float* __restrict__ clusters) {
    int t = threadIdx.x;            // 256 threads
    g_buf[0][t] = clusters[t];
    g_buf[1][t] = 0.0f;
}

// One iteration. grid = 1024 blocks (one image row each), 256 threads,
// each thread owns 4 contiguous columns.
// zbuf (may be null): buffer needed as *output two iterations from now* —
// unused this iteration, so block 0 zeroing it is race-free.
__global__ __launch_bounds__(256) void km_iter_kernel(
    const float* __restrict__ heatmap,
    const float* __restrict__ cin,
    float* __restrict__ cout,
    float* __restrict__ zbuf)
{
    __shared__ float2 s_cl[CC];
    __shared__ float  s_acc[2 * CC];

    const int t = threadIdx.x;
    if (zbuf != nullptr && blockIdx.x == 0) zbuf[t] = 0.0f;
    if (t < CC) s_cl[t] = reinterpret_cast<const float2*>(cin)[t];
    s_acc[t] = 0.0f;
    __syncthreads();

    const int row = blockIdx.x;
    const float frow = (float)row;
    const int col0 = t * 4;
    const float4 h4 = *reinterpret_cast<const float4*>(heatmap + row * WW + col0);
    const float fc0 = (float)col0;
    const float fc1 = (float)(col0 + 1);
    const float fc2 = (float)(col0 + 2);
    const float fc3 = (float)(col0 + 3);

    float b0 = CUDART_INF_F, b1 = CUDART_INF_F, b2 = CUDART_INF_F, b3 = CUDART_INF_F;
    int i0 = 0, i1 = 0, i2 = 0, i3 = 0;

    #pragma unroll 4
    for (int j = 0; j < CC; ++j) {
        const float2 cl = s_cl[j];
        const float dr = frow - cl.x;
        const float dr2 = dr * dr;

        // clamped squared distance: max(1, d2). Ordering of max(1, sqrt(d2))
        // equals ordering of max(1, d2); strict < keeps first index (argmin).
        float dc, d;
        dc = fc0 - cl.y; d = fmaxf(fmaf(dc, dc, dr2), 1.0f);
        if (d < b0) { b0 = d; i0 = j; }
        dc = fc1 - cl.y; d = fmaxf(fmaf(dc, dc, dr2), 1.0f);
        if (d < b1) { b1 = d; i1 = j; }
        dc = fc2 - cl.y; d = fmaxf(fmaf(dc, dc, dr2), 1.0f);
        if (d < b2) { b2 = d; i2 = j; }
        dc = fc3 - cl.y; d = fmaxf(fmaf(dc, dc, dr2), 1.0f);
        if (d < b3) { b3 = d; i3 = j; }
    }

    // weight = heatmap / max(1, sqrt(d2)) = h * rsqrt(clamped d2)
    const float w0 = h4.x * rsqrtf(b0);
    const float w1 = h4.y * rsqrtf(b1);
    const float w2 = h4.z * rsqrtf(b2);
    const float w3 = h4.w * rsqrtf(b3);

    atomicAdd(&s_acc[2 * i0],     frow * w0);
    atomicAdd(&s_acc[2 * i0 + 1], fc0  * w0);
    atomicAdd(&s_acc[2 * i1],     frow * w1);
    atomicAdd(&s_acc[2 * i1 + 1], fc1  * w1);
    atomicAdd(&s_acc[2 * i2],     frow * w2);
    atomicAdd(&s_acc[2 * i2 + 1], fc2  * w2);
    atomicAdd(&s_acc[2 * i3],     frow * w3);
    atomicAdd(&s_acc[2 * i3 + 1], fc3  * w3);

    __syncthreads();
    atomicAdd(&cout[t], s_acc[t]);
}

extern "C" void kernel_launch(void* const* d_in, const int* in_sizes, int n_in,
                              void* d_out, int out_size) {
    const float* clusters = (const float*)d_in[0];
    const float* heatmap  = (const float*)d_in[1];
    // defensive: identify by size (clusters = 256 elems, heatmap = 1M elems)
    if (n_in >= 2 && in_sizes[0] != 2 * CC) {
        const float* tmp = clusters; clusters = heatmap; heatmap = tmp;
    }
    float* out = (float*)d_out;

    float* base = nullptr;
    cudaGetSymbolAddress((void**)&base, g_buf);
    float* B[3] = { base, base + 2 * CC, base + 4 * CC };

    km_init_kernel<<<1, 256>>>(clusters);

    for (int k = 0; k < NITER; ++k) {
        const float* cin = B[k % 3];
        float* cout = (k == NITER - 1) ? out : B[(k + 1) % 3];
        float* zbuf;
        if (k == NITER - 2)      zbuf = out;            // zero d_out for last iter
        else if (k == NITER - 1) zbuf = nullptr;        // nothing left to zero
        else                     zbuf = B[(k + 2) % 3]; // output of iter k+1
        km_iter_kernel<<<HH, 256>>>(heatmap, cin, cout, zbuf);
    }
}

// round 2
// speedup vs baseline: 3.2081x; 3.2081x over previous
#include <cuda_runtime.h>
#include <math_constants.h>

#define HH 1024
#define WW 1024
#define CC 128
#define NITER 8
#define TS 32                 // tile side; grid = (1024/TS)^2 = 1024 blocks
#define TWO_RHO 43.85f        // 2 * sqrt(2) * 15.5 (tile half-diagonal), rounded up

// 3 rotating cluster buffers, each 2*CC floats (row,col interleaved)
__device__ float g_buf[3][2 * CC];

__global__ void km_init_kernel(const float* __restrict__ clusters) {
    int t = threadIdx.x;            // 256 threads
    g_buf[0][t] = clusters[t];
    g_buf[1][t] = 0.0f;
}

// One iteration. Block = one 32x32 pixel tile, 256 threads, 4 pixels each.
// Prologue: dedup clusters (exact-equality, keep lowest index), then cull to
// candidates that can win argmin for some pixel in this tile (exact bound).
__global__ __launch_bounds__(256) void km_iter_kernel(
    const float* __restrict__ heatmap,
    const float* __restrict__ cin,
    float* __restrict__ cout,
    float* __restrict__ zbuf)
{
    __shared__ float2   s_cl[CC];
    __shared__ float    s_acc[2 * CC];
    __shared__ float2   s_cand[CC];
    __shared__ int      s_cidx[CC];
    __shared__ unsigned s_mask[8];
    __shared__ float    s_wmin[8];

    const int t = threadIdx.x;
    if (zbuf != nullptr && blockIdx.x == 0) zbuf[t] = 0.0f;
    if (t < CC) s_cl[t] = reinterpret_cast<const float2*>(cin)[t];
    s_acc[t] = 0.0f;
    __syncthreads();

    const int tile_c = (blockIdx.x & 31) * TS;   // tile col origin
    const int tile_r = (blockIdx.x >> 5) * TS;   // tile row origin

    // ---- Phase A: dedup + center distances ----
    const float cy = (float)tile_r + 15.5f;      // tile center (row)
    const float cx = (float)tile_c + 15.5f;      // tile center (col)
    float d2c = CUDART_INF_F;
    if (t < CC) {
        const float2 c = s_cl[t];
        bool dup = false;
        for (int i = 0; i < t; ++i) {
            const float2 ci = s_cl[i];
            dup = dup || ((ci.x == c.x) && (ci.y == c.y));
        }
        if (!dup) {
            const float dr = cy - c.x, dc = cx - c.y;
            d2c = fmaf(dr, dr, dc * dc);
        }
    }
    // block-wide min of d2c
    float m = d2c;
    #pragma unroll
    for (int o = 16; o; o >>= 1) m = fminf(m, __shfl_xor_sync(0xFFFFFFFFu, m, o));
    if ((t & 31) == 0) s_wmin[t >> 5] = m;
    __syncthreads();
    float md2 = s_wmin[0];
    #pragma unroll
    for (int w = 1; w < 8; ++w) md2 = fminf(md2, s_wmin[w]);

    // conservative cull threshold (over-keeping is always correct)
    const float minD = sqrtf(md2);
    const float thr  = minD + TWO_RHO + 4.0f + 1e-5f * minD;
    const float thr2 = thr * thr;

    const bool keep = (t < CC) && (d2c <= thr2);
    const unsigned bal = __ballot_sync(0xFFFFFFFFu, keep);
    if ((t & 31) == 0) s_mask[t >> 5] = bal;
    __syncthreads();
    if (keep) {
        int rank = __popc(bal & ((1u << (t & 31)) - 1u));
        for (int w = 0; w < (t >> 5); ++w) rank += __popc(s_mask[w]);
        s_cand[rank] = s_cl[t];
        s_cidx[rank] = t;
    }
    const int ncand = __popc(s_mask[0]) + __popc(s_mask[1])
                    + __popc(s_mask[2]) + __popc(s_mask[3]);
    __syncthreads();

    // ---- Phase B: per-pixel argmin over candidates ----
    const int row  = tile_r + (t >> 3);
    const int col0 = tile_c + (t & 7) * 4;
    const float frow = (float)row;
    const float4 h4 = *reinterpret_cast<const float4*>(heatmap + row * WW + col0);
    const float fc0 = (float)col0;
    const float fc1 = (float)(col0 + 1);
    const float fc2 = (float)(col0 + 2);
    const float fc3 = (float)(col0 + 3);

    float b0 = CUDART_INF_F, b1 = CUDART_INF_F, b2 = CUDART_INF_F, b3 = CUDART_INF_F;
    int k0 = 0, k1 = 0, k2 = 0, k3 = 0;

    #pragma unroll 2
    for (int k = 0; k < ncand; ++k) {
        const float2 cl = s_cand[k];
        const float dr = frow - cl.x;
        const float dr2 = dr * dr;
        float dc, d;
        // ordering of max(1, sqrt(d2)) == ordering of max(1, d2); strict <
        // over candidates in index order keeps jnp.argmin's first-index rule
        dc = fc0 - cl.y; d = fmaxf(fmaf(dc, dc, dr2), 1.0f);
        if (d < b0) { b0 = d; k0 = k; }
        dc = fc1 - cl.y; d = fmaxf(fmaf(dc, dc, dr2), 1.0f);
        if (d < b1) { b1 = d; k1 = k; }
        dc = fc2 - cl.y; d = fmaxf(fmaf(dc, dc, dr2), 1.0f);
        if (d < b2) { b2 = d; k2 = k; }
        dc = fc3 - cl.y; d = fmaxf(fmaf(dc, dc, dr2), 1.0f);
        if (d < b3) { b3 = d; k3 = k; }
    }

    const int i0 = s_cidx[k0];
    const int i1 = s_cidx[k1];
    const int i2 = s_cidx[k2];
    const int i3 = s_cidx[k3];

    // weight = heatmap / max(1, sqrt(d2)) = h * rsqrt(clamped d2)
    const float w0 = h4.x * rsqrtf(b0);
    const float w1 = h4.y * rsqrtf(b1);
    const float w2 = h4.z * rsqrtf(b2);
    const float w3 = h4.w * rsqrtf(b3);

    // run-length merge of the 4 pixels (adjacent pixels usually share winner):
    // contribution = (frow * sum_w, sum_{fc*w})
    int cur = i0;
    float wsum = w0, cwsum = fc0 * w0;
    #define KM_STEP(ii, ww, fcx)                                        \
        if ((ii) == cur) { wsum += (ww); cwsum += (fcx) * (ww); }       \
        else {                                                          \
            atomicAdd(&s_acc[2 * cur],     frow * wsum);                \
            atomicAdd(&s_acc[2 * cur + 1], cwsum);                      \
            cur = (ii); wsum = (ww); cwsum = (fcx) * (ww);              \
        }
    KM_STEP(i1, w1, fc1)
    KM_STEP(i2, w2, fc2)
    KM_STEP(i3, w3, fc3)
    #undef KM_STEP
    atomicAdd(&s_acc[2 * cur],     frow * wsum);
    atomicAdd(&s_acc[2 * cur + 1], cwsum);

    __syncthreads();
    atomicAdd(&cout[t], s_acc[t]);
}

extern "C" void kernel_launch(void* const* d_in, const int* in_sizes, int n_in,
                              void* d_out, int out_size) {
    const float* clusters = (const float*)d_in[0];
    const float* heatmap  = (const float*)d_in[1];
    if (n_in >= 2 && in_sizes[0] != 2 * CC) {
        const float* tmp = clusters; clusters = heatmap; heatmap = tmp;
    }
    float* out = (float*)d_out;

    float* base = nullptr;
    cudaGetSymbolAddress((void**)&base, g_buf);
    float* B[3] = { base, base + 2 * CC, base + 4 * CC };

    km_init_kernel<<<1, 256>>>(clusters);

    for (int k = 0; k < NITER; ++k) {
        const float* cin = B[k % 3];
        float* cout = (k == NITER - 1) ? out : B[(k + 1) % 3];
        float* zbuf;
        if (k == NITER - 2)      zbuf = out;            // zero d_out for last iter
        else if (k == NITER - 1) zbuf = nullptr;
        else                     zbuf = B[(k + 2) % 3]; // output of iter k+1
        km_iter_kernel<<<1024, 256>>>(heatmap, cin, cout, zbuf);
    }
}

// round 3
// speedup vs baseline: 6.3620x; 1.9831x over previous
#include <cuda_runtime.h>
#include <math_constants.h>

#define HH 1024
#define WW 1024
#define CC 128
#define NITER 8
#define TS 32                 // tile side; grid = (1024/TS)^2 = 1024 blocks
#define TWO_RHO 43.85f        // 2 * sqrt(2) * 15.5 (tile half-diagonal), rounded up
#define FULLM 0xFFFFFFFFu

// ping-pong cluster buffers (row,col interleaved)
__device__ float  g_buf[2][2 * CC];
// per-iteration deduped candidate list (written by prep, read by iter)
__device__ float2 g_dpos[CC];
__device__ int    g_didx[CC];
__device__ int    g_nd;

// ---------------------------------------------------------------------------
// Prep (1 block, 256 threads): dedup clusters (exact bitwise equality, keep
// lowest index — a later bitwise-equal cluster can never win strict-< argmin),
// compact to g_dpos/g_didx/g_nd, and zero this iteration's output buffer.
// ---------------------------------------------------------------------------
__global__ void km_prep_kernel(const float* __restrict__ cin,
                               float* __restrict__ cout_zero)
{
    __shared__ float2   s_cl[CC];
    __shared__ unsigned s_mask[4];

    const int t = threadIdx.x;          // 256 threads
    cout_zero[t] = 0.0f;
    if (t < CC) s_cl[t] = reinterpret_cast<const float2*>(cin)[t];
    __syncthreads();

    bool keep = false;
    if (t < CC) {
        const float2 c = s_cl[t];
        bool dup = false;
        for (int i = 0; i < t; ++i) {
            const float2 ci = s_cl[i];
            dup = dup || ((ci.x == c.x) && (ci.y == c.y));
        }
        keep = !dup;
    }
    const unsigned bal = __ballot_sync(FULLM, keep);
    if (((t & 31) == 0) && (t < CC)) s_mask[t >> 5] = bal;
    __syncthreads();

    if (keep) {
        int rank = __popc(bal & ((1u << (t & 31)) - 1u));
        for (int w = 0; w < (t >> 5); ++w) rank += __popc(s_mask[w]);
        g_dpos[rank] = s_cl[t];
        g_didx[rank] = t;
    }
    if (t == 0)
        g_nd = __popc(s_mask[0]) + __popc(s_mask[1])
             + __popc(s_mask[2]) + __popc(s_mask[3]);
}

// ---------------------------------------------------------------------------
// One iteration. Block = one 32x32 pixel tile, 256 threads, 4 pixels each.
// ---------------------------------------------------------------------------
__global__ __launch_bounds__(256) void km_iter_kernel(
    const float* __restrict__ heatmap,
    float* __restrict__ cout)
{
    __shared__ float2   s_cand[CC];
    __shared__ int      s_cidx[CC];
    __shared__ float    s_acc[2 * CC];
    __shared__ unsigned s_mask[4];
    __shared__ float    s_wmin[8];

    const int t = threadIdx.x;
    s_acc[t] = 0.0f;

    const int nd = g_nd;                          // uniform LDG (L2 hit)
    const int tile_c = (blockIdx.x & 31) * TS;
    const int tile_r = (blockIdx.x >> 5) * TS;

    // ---- Phase A: center-distance cull over deduped list ----
    const float cy = (float)tile_r + 15.5f;
    const float cx = (float)tile_c + 15.5f;
    float d2c = CUDART_INF_F;
    float2 cpos = make_float2(0.f, 0.f);
    if (t < nd) {
        cpos = g_dpos[t];
        const float dr = cy - cpos.x, dc = cx - cpos.y;
        d2c = fmaf(dr, dr, dc * dc);
    }
    float m = d2c;
    #pragma unroll
    for (int o = 16; o; o >>= 1) m = fminf(m, __shfl_xor_sync(FULLM, m, o));
    if ((t & 31) == 0) s_wmin[t >> 5] = m;
    __syncthreads();
    float md2 = s_wmin[0];
    #pragma unroll
    for (int w = 1; w < 8; ++w) md2 = fminf(md2, s_wmin[w]);

    // conservative threshold: cluster can win argmin for some pixel in tile
    // only if d(center,c) <= minD + 2*rho; margin makes fp error safe
    const float minD = sqrtf(md2);
    const float thr  = minD + TWO_RHO + 4.0f + 1e-5f * minD;
    const float thr2 = thr * thr;

    const bool keep = (t < nd) && (d2c <= thr2);
    const unsigned bal = __ballot_sync(FULLM, keep);
    if (((t & 31) == 0) && ((t >> 5) < 4)) s_mask[t >> 5] = bal;
    __syncthreads();
    if (keep) {
        int rank = __popc(bal & ((1u << (t & 31)) - 1u));
        for (int w = 0; w < (t >> 5); ++w) rank += __popc(s_mask[w]);
        s_cand[rank] = cpos;
        s_cidx[rank] = g_didx[t];
    }
    const int ncand = __popc(s_mask[0]) + __popc(s_mask[1])
                    + __popc(s_mask[2]) + __popc(s_mask[3]);
    __syncthreads();

    // ---- Phase B: per-pixel argmin over candidates (index order kept) ----
    const int row  = tile_r + (t >> 3);
    const int col0 = tile_c + (t & 7) * 4;
    const float frow = (float)row;
    const float4 h4 = *reinterpret_cast<const float4*>(heatmap + row * WW + col0);
    const float fc0 = (float)col0;
    const float fc1 = (float)(col0 + 1);
    const float fc2 = (float)(col0 + 2);
    const float fc3 = (float)(col0 + 3);

    float b0 = CUDART_INF_F, b1 = CUDART_INF_F, b2 = CUDART_INF_F, b3 = CUDART_INF_F;
    int k0 = 0, k1 = 0, k2 = 0, k3 = 0;

    #pragma unroll 2
    for (int k = 0; k < ncand; ++k) {
        const float2 cl = s_cand[k];
        const float dr = frow - cl.x;
        const float dr2 = dr * dr;
        float dc, d;
        // ordering of max(1,sqrt(d2)) == ordering of max(1,d2); strict <
        dc = fc0 - cl.y; d = fmaxf(fmaf(dc, dc, dr2), 1.0f);
        if (d < b0) { b0 = d; k0 = k; }
        dc = fc1 - cl.y; d = fmaxf(fmaf(dc, dc, dr2), 1.0f);
        if (d < b1) { b1 = d; k1 = k; }
        dc = fc2 - cl.y; d = fmaxf(fmaf(dc, dc, dr2), 1.0f);
        if (d < b2) { b2 = d; k2 = k; }
        dc = fc3 - cl.y; d = fmaxf(fmaf(dc, dc, dr2), 1.0f);
        if (d < b3) { b3 = d; k3 = k; }
    }

    const int i0 = s_cidx[k0];
    const int i1 = s_cidx[k1];
    const int i2 = s_cidx[k2];
    const int i3 = s_cidx[k3];

    // weight = heatmap / max(1, sqrt(d2)) = h * rsqrt(clamped d2)
    const float w0 = h4.x * rsqrtf(b0);
    const float w1 = h4.y * rsqrtf(b1);
    const float w2 = h4.z * rsqrtf(b2);
    const float w3 = h4.w * rsqrtf(b3);

    // ---- scatter: uniform-warp fast path, run-length fallback ----
    const bool uni4 = (i0 == i1) & (i1 == i2) & (i2 == i3);
    const int  u    = __shfl_sync(FULLM, i0, 0);
    const bool alluni = __all_sync(FULLM, uni4 && (i0 == u));

    if (alluni) {
        float rsum = frow * ((w0 + w1) + (w2 + w3));
        float csum = (fc0 * w0 + fc1 * w1) + (fc2 * w2 + fc3 * w3);
        #pragma unroll
        for (int o = 16; o; o >>= 1) {
            rsum += __shfl_xor_sync(FULLM, rsum, o);
            csum += __shfl_xor_sync(FULLM, csum, o);
        }
        if ((t & 31) == 0) {
            atomicAdd(&s_acc[2 * u],     rsum);
            atomicAdd(&s_acc[2 * u + 1], csum);
        }
    } else {
        int cur = i0;
        float wsum = w0, cwsum = fc0 * w0;
        #define KM_STEP(ii, ww, fcx)                                    \
            if ((ii) == cur) { wsum += (ww); cwsum += (fcx) * (ww); }   \
            else {                                                      \
                atomicAdd(&s_acc[2 * cur],     frow * wsum);            \
                atomicAdd(&s_acc[2 * cur + 1], cwsum);                  \
                cur = (ii); wsum = (ww); cwsum = (fcx) * (ww);          \
            }
        KM_STEP(i1, w1, fc1)
        KM_STEP(i2, w2, fc2)
        KM_STEP(i3, w3, fc3)
        #undef KM_STEP
        atomicAdd(&s_acc[2 * cur],     frow * wsum);
        atomicAdd(&s_acc[2 * cur + 1], cwsum);
    }

    __syncthreads();
    atomicAdd(&cout[t], s_acc[t]);
}

extern "C" void kernel_launch(void* const* d_in, const int* in_sizes, int n_in,
                              void* d_out, int out_size) {
    const float* clusters = (const float*)d_in[0];
    const float* heatmap  = (const float*)d_in[1];
    if (n_in >= 2 && in_sizes[0] != 2 * CC) {
        const float* tmp = clusters; clusters = heatmap; heatmap = tmp;
    }
    float* out = (float*)d_out;

    float* base = nullptr;
    cudaGetSymbolAddress((void**)&base, g_buf);
    float* B[2] = { base, base + 2 * CC };

    for (int k = 0; k < NITER; ++k) {
        const float* cin = (k == 0) ? clusters : B[(k + 1) & 1];
        float* cout = (k == NITER - 1) ? out : B[k & 1];
        km_prep_kernel<<<1, 256>>>(cin, cout);      // dedup + zero cout
        km_iter_kernel<<<1024, 256>>>(heatmap, cout);
    }
}

// round 4
// speedup vs baseline: 10.9718x; 1.7246x over previous
#include <cuda_runtime.h>
#include <math_constants.h>

#define HH 1024
#define WW 1024
#define CC 128
#define NITER 8
#define TS 32                 // tile side; grid = (1024/TS)^2 = 1024 blocks
#define TWO_RHO 43.85f        // 2*sqrt(2)*15.5 (tile half-diagonal), rounded up
#define FULLM 0xFFFFFFFFu
#define NBLK 1024

// 4 rotating cluster position buffers (row,col interleaved)
__device__ float g_pos[4][2 * CC];
// software grid barrier state (persists across replays; targets are base-relative)
__device__ unsigned g_bar_count = 0;
__device__ volatile unsigned g_bar_gen = 0;

__device__ __forceinline__ void grid_barrier(unsigned target) {
    __syncthreads();
    if (threadIdx.x == 0) {
        __threadfence();
        unsigned arr = atomicAdd(&g_bar_count, 1u);
        if (arr == NBLK - 1u) {
            atomicExch(&g_bar_count, 0u);     // reset before releasing
            __threadfence();
            atomicAdd((unsigned*)&g_bar_gen, 1u);
        } else {
            while ((int)(g_bar_gen - target) < 0) __nanosleep(64);
            __threadfence();
        }
    }
    __syncthreads();
}

__global__ void __launch_bounds__(256, 8) km_all_kernel(
    const float* __restrict__ clusters,
    const float* __restrict__ heatmap,
    float* __restrict__ out)
{
    __shared__ float2   s_cl[CC];
    __shared__ float2   s_cand[CC];
    __shared__ int      s_cidx[CC];
    __shared__ float    s_acc[2 * CC];
    __shared__ unsigned s_mask[4];
    __shared__ float    s_wmin[8];

    const int t = threadIdx.x;
    const int tile_c = (blockIdx.x & 31) * TS;
    const int tile_r = (blockIdx.x >> 5) * TS;
    const int row  = tile_r + (t >> 3);
    const int col0 = tile_c + (t & 7) * 4;
    const float frow = (float)row;
    const float fc0 = (float)col0;
    const float fc1 = (float)(col0 + 1);
    const float fc2 = (float)(col0 + 2);
    const float fc3 = (float)(col0 + 3);
    const float cy = (float)tile_r + 15.5f;
    const float cx = (float)tile_c + 15.5f;

    // base generation (monotone across graph replays); all blocks read it
    // before any bump can happen (bump needs all 1024 arrivals)
    unsigned tgt = g_bar_gen;

    // pre-loop: zero the output buffer of iter 0 (P1)
    if (blockIdx.x == 0) g_pos[1][t] = 0.0f;
    grid_barrier(++tgt);

    #pragma unroll 1
    for (int k = 0; k < NITER; ++k) {
        const float* cin = (k == 0) ? clusters : &g_pos[k & 3][0];
        float* cout = (k == NITER - 1) ? out : &g_pos[(k + 1) & 3][0];

        s_acc[t] = 0.0f;

        // ---- Phase A: cull + fused dedup ----
        float d2c = CUDART_INF_F;
        float2 cpos = make_float2(0.f, 0.f);
        if (t < CC) {
            // bypass L1: positions are produced via L2 atomics by other SMs
            cpos = __ldcg(reinterpret_cast<const float2*>(cin) + t);
            s_cl[t] = cpos;
            const float dr = cy - cpos.x, dc = cx - cpos.y;
            d2c = fmaf(dr, dr, dc * dc);
        }
        float m = d2c;
        #pragma unroll
        for (int o = 16; o; o >>= 1) m = fminf(m, __shfl_xor_sync(FULLM, m, o));
        if ((t & 31) == 0) s_wmin[t >> 5] = m;
        __syncthreads();                       // s_wmin + s_cl visible
        float md2 = s_wmin[0];
        #pragma unroll
        for (int w = 1; w < 8; ++w) md2 = fminf(md2, s_wmin[w]);

        // cluster can win argmin for some pixel in tile only if
        // d(center,c) <= minD + 2*rho; margin makes fp error conservative
        const float minD = sqrtf(md2);
        const float thr  = minD + TWO_RHO + 4.0f + 1e-5f * minD;
        const float thr2 = thr * thr;

        bool keep = (t < CC) && (d2c <= thr2);
        if (keep) {
            // drop exact-position duplicates: a later bitwise-equal cluster
            // can never win strict-< argmin (first index wins)
            for (int i = 0; i < t; ++i) {
                const float2 ci = s_cl[i];
                if ((ci.x == cpos.x) && (ci.y == cpos.y)) { keep = false; break; }
            }
        }
        const unsigned bal = __ballot_sync(FULLM, keep);
        if (((t & 31) == 0) && ((t >> 5) < 4)) s_mask[t >> 5] = bal;
        __syncthreads();
        if (keep) {
            int rank = __popc(bal & ((1u << (t & 31)) - 1u));
            for (int w = 0; w < (t >> 5); ++w) rank += __popc(s_mask[w]);
            s_cand[rank] = cpos;
            s_cidx[rank] = t;
        }
        const int ncand = __popc(s_mask[0]) + __popc(s_mask[1])
                        + __popc(s_mask[2]) + __popc(s_mask[3]);
        __syncthreads();

        // ---- Phase B: per-pixel argmin (candidates in index order) ----
        const float4 h4 = *reinterpret_cast<const float4*>(heatmap + row * WW + col0);

        float b0 = CUDART_INF_F, b1 = CUDART_INF_F, b2 = CUDART_INF_F, b3 = CUDART_INF_F;
        int k0 = 0, k1 = 0, k2 = 0, k3 = 0;

        #pragma unroll 2
        for (int j = 0; j < ncand; ++j) {
            const float2 cl = s_cand[j];
            const float dr = frow - cl.x;
            const float dr2 = dr * dr;
            float dc, d;
            // ordering of max(1,sqrt(d2)) == ordering of max(1,d2); strict <
            dc = fc0 - cl.y; d = fmaxf(fmaf(dc, dc, dr2), 1.0f);
            if (d < b0) { b0 = d; k0 = j; }
            dc = fc1 - cl.y; d = fmaxf(fmaf(dc, dc, dr2), 1.0f);
            if (d < b1) { b1 = d; k1 = j; }
            dc = fc2 - cl.y; d = fmaxf(fmaf(dc, dc, dr2), 1.0f);
            if (d < b2) { b2 = d; k2 = j; }
            dc = fc3 - cl.y; d = fmaxf(fmaf(dc, dc, dr2), 1.0f);
            if (d < b3) { b3 = d; k3 = j; }
        }

        const int i0 = s_cidx[k0];
        const int i1 = s_cidx[k1];
        const int i2 = s_cidx[k2];
        const int i3 = s_cidx[k3];

        // weight = heatmap / max(1, sqrt(d2)) = h * rsqrt(clamped d2)
        const float w0 = h4.x * rsqrtf(b0);
        const float w1 = h4.y * rsqrtf(b1);
        const float w2 = h4.z * rsqrtf(b2);
        const float w3 = h4.w * rsqrtf(b3);

        // ---- scatter: uniform-warp fast path, run-length fallback ----
        const bool uni4 = (i0 == i1) & (i1 == i2) & (i2 == i3);
        const int  u    = __shfl_sync(FULLM, i0, 0);
        const bool alluni = __all_sync(FULLM, uni4 && (i0 == u));

        if (alluni) {
            float rsum = frow * ((w0 + w1) + (w2 + w3));
            float csum = (fc0 * w0 + fc1 * w1) + (fc2 * w2 + fc3 * w3);
            #pragma unroll
            for (int o = 16; o; o >>= 1) {
                rsum += __shfl_xor_sync(FULLM, rsum, o);
                csum += __shfl_xor_sync(FULLM, csum, o);
            }
            if ((t & 31) == 0) {
                atomicAdd(&s_acc[2 * u],     rsum);
                atomicAdd(&s_acc[2 * u + 1], csum);
            }
        } else {
            int cur = i0;
            float wsum = w0, cwsum = fc0 * w0;
            #define KM_STEP(ii, ww, fcx)                                    \
                if ((ii) == cur) { wsum += (ww); cwsum += (fcx) * (ww); }   \
                else {                                                      \
                    atomicAdd(&s_acc[2 * cur],     frow * wsum);            \
                    atomicAdd(&s_acc[2 * cur + 1], cwsum);                  \
                    cur = (ii); wsum = (ww); cwsum = (fcx) * (ww);          \
                }
            KM_STEP(i1, w1, fc1)
            KM_STEP(i2, w2, fc2)
            KM_STEP(i3, w3, fc3)
            #undef KM_STEP
            atomicAdd(&s_acc[2 * cur],     frow * wsum);
            atomicAdd(&s_acc[2 * cur + 1], cwsum);
        }

        __syncthreads();
        // global accumulate; skip zeros (all contributions are >= +0)
        const float v = s_acc[t];
        if (v != 0.0f) atomicAdd(&cout[t], v);

        // block 0 zeroes the output buffer of iteration k+2 (idle this iter);
        // the barrier below publishes it before it is written
        if (blockIdx.x == 0) {
            if (k == NITER - 2)      { /* nothing left to zero */ }
            else if (k == NITER - 3) out[t] = 0.0f;            // iter 7 writes d_out
            else                     g_pos[(k + 2) & 3][t] = 0.0f;
        }

        if (k < NITER - 1) grid_barrier(++tgt);
    }
}

extern "C" void kernel_launch(void* const* d_in, const int* in_sizes, int n_in,
                              void* d_out, int out_size) {
    const float* clusters = (const float*)d_in[0];
    const float* heatmap  = (const float*)d_in[1];
    if (n_in >= 2 && in_sizes[0] != 2 * CC) {
        const float* tmp = clusters; clusters = heatmap; heatmap = tmp;
    }
    km_all_kernel<<<NBLK, 256>>>(clusters, heatmap, (float*)d_out);
}